// round 13
// baseline (speedup 1.0000x reference)
#include <cuda_runtime.h>
#include <cuda_bf16.h>
#include <cstdint>

// ============================================================================
// LogMM: out[16384,1024] = log( x[16384,1024] @ matrix[1024,1024] )
// (reference's big/small branches sum exactly to log(max(y,tiny)))
//
// R13: exact per-SM tile budget using REAL %smid (R7 guessed placement and
// lost). grid=304 (=2/SM on 148 or 152 SMs; wave-1 full residency) -> the two
// CTAs on SM s claim slot 0/1 via atomicAdd(g_sm_slot[smid]) and process the
// contiguous tile range [7s, 7s+7) split 4/3. Makespan = 7 tile-times/SM
// (mean 6.92) vs ~8 under random wave quantization. Skeleton = R5: persistent
// chunk streaming (no pipeline drain), 128x128 tile, BK=64, 3-stage cp.async,
// 2 CTAs/SM, fused __logf epilogue.
// ============================================================================

#define M_TOTAL 16384
#define N_TOTAL 1024
#define K_TOTAL 1024
#define TILE_M 128
#define TILE_N 128
#define BK 64                    // bf16 per K-chunk (128 B per row)
#define NCHUNK (K_TOTAL / BK)    // 16
#define NSTAGE 3
#define NTILES ((M_TOTAL / TILE_M) * (N_TOTAL / TILE_N))  // 1024
#define TILES_PER_SM 7           // 147 SMs x 7 = 1029 >= 1024 (clamped)
#define GRID_GEMM 304            // 2 x 152 (covers GB300's 152 SMs; extras exit)

static constexpr int SMEM_PAD = 1024;
static constexpr int TILE_BYTES = TILE_M * 128;     // 16384
static constexpr int BUF_STRIDE = 2 * TILE_BYTES;   // 32768
static constexpr int SMEM_TOTAL = SMEM_PAD + NSTAGE * BUF_STRIDE;  // 99328

// Scratch bf16 buffers + per-SM slot counters (device globals: allocation-free)
__device__ __align__(256) __nv_bfloat16 g_xb[(size_t)M_TOTAL * K_TOTAL];
__device__ __align__(256) __nv_bfloat16 g_bt[(size_t)N_TOTAL * K_TOTAL];
__device__ int g_sm_slot[256];

// ---------------------------------------------------------------------------
// Helpers
// ---------------------------------------------------------------------------
__device__ __forceinline__ uint32_t smem_u32(const void* p) {
    uint32_t a;
    asm("{ .reg .u64 t; cvta.to.shared.u64 t, %1; cvt.u32.u64 %0, t; }" : "=r"(a) : "l"(p));
    return a;
}
__device__ __forceinline__ uint32_t sw128(uint32_t off) {
    return off ^ ((off >> 3) & 0x70);
}
__device__ __forceinline__ void cp_async16(uint32_t smem_addr, const void* gptr) {
    asm volatile("cp.async.cg.shared.global [%0], [%1], 16;"
                 :: "r"(smem_addr), "l"(gptr) : "memory");
}
#define CP_COMMIT() asm volatile("cp.async.commit_group;" ::: "memory")
#define CP_WAIT(n)  asm volatile("cp.async.wait_group %0;" :: "n"(n) : "memory")

__device__ __forceinline__ void ldsm_x4(uint32_t* r, uint32_t addr) {
    asm volatile("ldmatrix.sync.aligned.m8n8.x4.shared.b16 {%0, %1, %2, %3}, [%4];"
                 : "=r"(r[0]), "=r"(r[1]), "=r"(r[2]), "=r"(r[3]) : "r"(addr));
}
__device__ __forceinline__ void mma16816(float* c, const uint32_t* a, const uint32_t* b) {
    asm volatile("mma.sync.aligned.m16n8k16.row.col.f32.bf16.bf16.f32 "
                 "{%0, %1, %2, %3}, {%4, %5, %6, %7}, {%8, %9}, {%0, %1, %2, %3};"
                 : "+f"(c[0]), "+f"(c[1]), "+f"(c[2]), "+f"(c[3])
                 : "r"(a[0]), "r"(a[1]), "r"(a[2]), "r"(a[3]), "r"(b[0]), "r"(b[1]));
}
__device__ __forceinline__ uint32_t pack_bf16x2(float a, float b) {
    __nv_bfloat162 h = __floats2bfloat162_rn(a, b);
    return *reinterpret_cast<uint32_t*>(&h);
}

// ---------------------------------------------------------------------------
// Fused conversion kernel (single launch; also resets per-SM slot counters):
//   blocks [0, 8192):         x fp32 -> g_xb bf16 (8 elems/thread)
//   blocks [8192, 8192+1024): matrix[K,N] -> g_bt[N,K] bf16 (32x32 tiles)
// ---------------------------------------------------------------------------
#define CVT_X_BLOCKS (M_TOTAL * K_TOTAL / (256 * 8))   // 8192
#define CVT_T_BLOCKS ((K_TOTAL / 32) * (N_TOTAL / 32)) // 1024

__global__ void __launch_bounds__(256)
cvt_kernel(const float* __restrict__ x, const float* __restrict__ m) {
    int tid = threadIdx.x;
    if (blockIdx.x == 0) g_sm_slot[tid] = 0;   // reset slot counters per launch
    if (blockIdx.x < CVT_X_BLOCKS) {
        size_t i = ((size_t)blockIdx.x * 256 + tid) * 8;
        float4 a = *reinterpret_cast<const float4*>(x + i);
        float4 b = *reinterpret_cast<const float4*>(x + i + 4);
        uint4 o;
        o.x = pack_bf16x2(a.x, a.y);
        o.y = pack_bf16x2(a.z, a.w);
        o.z = pack_bf16x2(b.x, b.y);
        o.w = pack_bf16x2(b.z, b.w);
        *reinterpret_cast<uint4*>(g_xb + i) = o;
    } else {
        __shared__ float tile[32][33];
        int t = blockIdx.x - CVT_X_BLOCKS;
        int bn = (t & 31) * 32;          // n block
        int bk = (t >> 5) * 32;          // k block
        int lane = tid & 31;
        int rr = tid >> 5;               // 0..7
#pragma unroll
        for (int i = 0; i < 4; i++) {
            int row = i * 8 + rr;        // k within tile
            tile[row][lane] = m[(size_t)(bk + row) * N_TOTAL + bn + lane];
        }
        __syncthreads();
#pragma unroll
        for (int i = 0; i < 4; i++) {
            int row = i * 8 + rr;        // n within tile
            g_bt[(size_t)(bn + row) * K_TOTAL + bk + lane] =
                __float2bfloat16_rn(tile[lane][row]);
        }
    }
}

// ---------------------------------------------------------------------------
// GEMM + log kernel (persistent streaming, smid-budgeted contiguous tiles)
// ---------------------------------------------------------------------------
// Issue cp.asyncs for global chunk g of this CTA's contiguous tile range.
__device__ __forceinline__ void issue_chunk(uint32_t smem_base, int g, int t_begin, int tid) {
    int t = t_begin + (g >> 4);          // contiguous tiles
    int kc = g & (NCHUNK - 1);
    int m0 = (t >> 3) * TILE_M;          // t = m_idx*8 + n_idx
    int n0 = (t & 7) * TILE_N;
    const uint4* Ag = reinterpret_cast<const uint4*>(g_xb + (size_t)m0 * K_TOTAL + kc * BK);
    const uint4* Bg = reinterpret_cast<const uint4*>(g_bt + (size_t)n0 * K_TOTAL + kc * BK);
    uint32_t Abase = smem_base + SMEM_PAD + (g % NSTAGE) * BUF_STRIDE;
    uint32_t Bbase = Abase + TILE_BYTES;
#pragma unroll
    for (int i = 0; i < 4; i++) {
        int cc = i * 256 + tid;           // 1024 16B-chunks per tile
        int row = cc >> 3;                // 0..127
        int c16 = cc & 7;                 // 16B chunk within 128B row
        uint32_t sw = sw128((uint32_t)(row * 128 + c16 * 16));
        cp_async16(Abase + sw, Ag + (size_t)row * (K_TOTAL / 8) + c16);
        cp_async16(Bbase + sw, Bg + (size_t)row * (K_TOTAL / 8) + c16);
    }
    CP_COMMIT();
}

__global__ void __launch_bounds__(256, 2)
logmm_gemm_kernel(float* __restrict__ out) {
    extern __shared__ char smem[];
    __shared__ int s_slot;
    uint32_t sb = smem_u32(smem);
    int tid = threadIdx.x;
    int wid = tid >> 5;
    int lid = tid & 31;

    // 8 warps: warp_m in {0,1} (64 rows), warp_n in {0..3} (32 cols)
    int warp_m = wid >> 2;
    int warp_n = wid & 3;

    // Ground-truth SM identity; two co-resident CTAs claim slots 0/1.
    uint32_t smid;
    asm("mov.u32 %0, %%smid;" : "=r"(smid));
    if (tid == 0) s_slot = atomicAdd(&g_sm_slot[smid & 255], 1);
    __syncthreads();
    int slot = s_slot;

    // SM s owns tiles [7s, 7s+7): slot0 -> first 4, slot1 -> last 3.
    int t_begin = (int)smid * TILES_PER_SM + (slot == 0 ? 0 : 4);
    int cnt = (slot == 0) ? 4 : (slot == 1 ? 3 : 0);
    int avail = NTILES - t_begin;
    int my_tiles = cnt < avail ? cnt : avail;
    if (my_tiles <= 0) return;
    int G = my_tiles * NCHUNK;

    float acc[4][4][4];
#pragma unroll
    for (int mf = 0; mf < 4; mf++)
#pragma unroll
        for (int nf = 0; nf < 4; nf++)
#pragma unroll
            for (int i = 0; i < 4; i++) acc[mf][nf][i] = 0.0f;

    // Prologue: fill 2 of 3 stages
    issue_chunk(sb, 0, t_begin, tid);
    issue_chunk(sb, 1, t_begin, tid);

    for (int g = 0; g < G; g++) {
        if (g == G - 1) { CP_WAIT(0); } else { CP_WAIT(1); }
        __syncthreads();

        // Prefetch chunk g+2 (may belong to the NEXT tile -> no drain)
        if (g + 2 < G) issue_chunk(sb, g + 2, t_begin, tid);

        uint32_t Ab = sb + SMEM_PAD + (g % NSTAGE) * BUF_STRIDE;
        uint32_t Bb = Ab + TILE_BYTES;
#pragma unroll
        for (int ks = 0; ks < 4; ks++) {
            uint32_t a[4][4], b[2][4];
#pragma unroll
            for (int mf = 0; mf < 4; mf++) {
                int row = warp_m * 64 + mf * 16 + (lid & 15);
                uint32_t off = (uint32_t)(row * 128 + ks * 32 + ((lid >> 4) << 4));
                ldsm_x4(a[mf], Ab + sw128(off));
            }
#pragma unroll
            for (int p = 0; p < 2; p++) {
                int row = warp_n * 32 + p * 16 + (lid & 7) + ((lid >> 4) << 3);
                uint32_t off = (uint32_t)(row * 128 + ks * 32 + (((lid >> 3) & 1) << 4));
                ldsm_x4(b[p], Bb + sw128(off));
            }
#pragma unroll
            for (int mf = 0; mf < 4; mf++)
#pragma unroll
                for (int nf = 0; nf < 4; nf++)
                    mma16816(acc[mf][nf], a[mf], b[nf >> 1] + (nf & 1) * 2);
        }

        // Tile finished? Epilogue overlapped with in-flight next-tile loads.
        if ((g & (NCHUNK - 1)) == NCHUNK - 1) {
            int t = t_begin + (g >> 4);
            int m0 = (t >> 3) * TILE_M;
            int n0 = (t & 7) * TILE_N;
#pragma unroll
            for (int mf = 0; mf < 4; mf++) {
#pragma unroll
                for (int nf = 0; nf < 4; nf++) {
                    int row0 = m0 + warp_m * 64 + mf * 16 + (lid >> 2);
                    int col = n0 + warp_n * 32 + nf * 8 + (lid & 3) * 2;
                    float2 v0, v1;
                    v0.x = __logf(fmaxf(acc[mf][nf][0], 1.17549435e-38f));
                    v0.y = __logf(fmaxf(acc[mf][nf][1], 1.17549435e-38f));
                    v1.x = __logf(fmaxf(acc[mf][nf][2], 1.17549435e-38f));
                    v1.y = __logf(fmaxf(acc[mf][nf][3], 1.17549435e-38f));
                    *reinterpret_cast<float2*>(out + (size_t)row0 * N_TOTAL + col) = v0;
                    *reinterpret_cast<float2*>(out + (size_t)(row0 + 8) * N_TOTAL + col) = v1;
                    acc[mf][nf][0] = 0.0f;
                    acc[mf][nf][1] = 0.0f;
                    acc[mf][nf][2] = 0.0f;
                    acc[mf][nf][3] = 0.0f;
                }
            }
        }
    }
}

// ---------------------------------------------------------------------------
// Launch
// ---------------------------------------------------------------------------
extern "C" void kernel_launch(void* const* d_in, const int* in_sizes, int n_in,
                              void* d_out, int out_size) {
    const float* x = (const float*)d_in[0];
    const float* mat = (const float*)d_in[1];
    if (n_in >= 2 && in_sizes[0] == N_TOTAL * K_TOTAL && in_sizes[1] == M_TOTAL * K_TOTAL) {
        const float* t = x; x = mat; mat = t;
    }
    float* out = (float*)d_out;

    cudaFuncSetAttribute(logmm_gemm_kernel,
                         cudaFuncAttributeMaxDynamicSharedMemorySize, SMEM_TOTAL);

    cvt_kernel<<<CVT_X_BLOCKS + CVT_T_BLOCKS, 256>>>(x, mat);
    logmm_gemm_kernel<<<GRID_GEMM, 256, SMEM_TOTAL>>>(out);
}

// round 14
// speedup vs baseline: 1.3452x; 1.3452x over previous
#include <cuda_runtime.h>
#include <cuda_bf16.h>
#include <cstdint>

// ============================================================================
// LogMM: out[16384,1024] = log( x[16384,1024] @ matrix[1024,1024] )
// (reference's big/small branches sum exactly to log(max(y,tiny)))
//
// R14: R5 champion (102.9us) byte-identical mainloop; single delta:
// epilogue uses st.global.cs streaming stores so the 64MB write-once output
// doesn't evict the L2-resident A panel (32MB, re-read 8x) and per-CTA B
// panel (static stride 296 = 0 mod 8 -> each CTA's tiles share n0).
// All scheduling variants (R6-R9, R12, R13) measured worse; this is the
// banked optimum of the mma.sync design space.
// ============================================================================

#define M_TOTAL 16384
#define N_TOTAL 1024
#define K_TOTAL 1024
#define TILE_M 128
#define TILE_N 128
#define BK 64                    // bf16 per K-chunk (128 B per row)
#define NCHUNK (K_TOTAL / BK)    // 16
#define NSTAGE 3
#define NTILES ((M_TOTAL / TILE_M) * (N_TOTAL / TILE_N))  // 1024
#define GRID_GEMM 296            // 2 CTAs/SM x 148 SMs

static constexpr int SMEM_TILES = 1024;
static constexpr int TILE_BYTES = TILE_M * 128;     // 16384
static constexpr int BUF_STRIDE = 2 * TILE_BYTES;   // 32768
static constexpr int SMEM_TOTAL = SMEM_TILES + NSTAGE * BUF_STRIDE;  // 99328

// Scratch bf16 buffers (device globals: allocation-free)
__device__ __align__(256) __nv_bfloat16 g_xb[(size_t)M_TOTAL * K_TOTAL];
__device__ __align__(256) __nv_bfloat16 g_bt[(size_t)N_TOTAL * K_TOTAL];

// ---------------------------------------------------------------------------
// Helpers
// ---------------------------------------------------------------------------
__device__ __forceinline__ uint32_t smem_u32(const void* p) {
    uint32_t a;
    asm("{ .reg .u64 t; cvta.to.shared.u64 t, %1; cvt.u32.u64 %0, t; }" : "=r"(a) : "l"(p));
    return a;
}
__device__ __forceinline__ uint32_t sw128(uint32_t off) {
    return off ^ ((off >> 3) & 0x70);
}
__device__ __forceinline__ void cp_async16(uint32_t smem_addr, const void* gptr) {
    asm volatile("cp.async.cg.shared.global [%0], [%1], 16;"
                 :: "r"(smem_addr), "l"(gptr) : "memory");
}
#define CP_COMMIT() asm volatile("cp.async.commit_group;" ::: "memory")
#define CP_WAIT(n)  asm volatile("cp.async.wait_group %0;" :: "n"(n) : "memory")

__device__ __forceinline__ void ldsm_x4(uint32_t* r, uint32_t addr) {
    asm volatile("ldmatrix.sync.aligned.m8n8.x4.shared.b16 {%0, %1, %2, %3}, [%4];"
                 : "=r"(r[0]), "=r"(r[1]), "=r"(r[2]), "=r"(r[3]) : "r"(addr));
}
__device__ __forceinline__ void mma16816(float* c, const uint32_t* a, const uint32_t* b) {
    asm volatile("mma.sync.aligned.m16n8k16.row.col.f32.bf16.bf16.f32 "
                 "{%0, %1, %2, %3}, {%4, %5, %6, %7}, {%8, %9}, {%0, %1, %2, %3};"
                 : "+f"(c[0]), "+f"(c[1]), "+f"(c[2]), "+f"(c[3])
                 : "r"(a[0]), "r"(a[1]), "r"(a[2]), "r"(a[3]), "r"(b[0]), "r"(b[1]));
}
__device__ __forceinline__ uint32_t pack_bf16x2(float a, float b) {
    __nv_bfloat162 h = __floats2bfloat162_rn(a, b);
    return *reinterpret_cast<uint32_t*>(&h);
}
// Streaming (evict-first) 8-byte store: output is write-once; don't pollute L2.
__device__ __forceinline__ void stg_cs_f2(float* p, float2 v) {
    asm volatile("st.global.cs.v2.f32 [%0], {%1, %2};"
                 :: "l"(p), "f"(v.x), "f"(v.y) : "memory");
}

// ---------------------------------------------------------------------------
// Fused conversion kernel (single launch):
//   blocks [0, 8192):         x fp32 -> g_xb bf16 (8 elems/thread)
//   blocks [8192, 8192+1024): matrix[K,N] -> g_bt[N,K] bf16 (32x32 tiles)
// ---------------------------------------------------------------------------
#define CVT_X_BLOCKS (M_TOTAL * K_TOTAL / (256 * 8))   // 8192
#define CVT_T_BLOCKS ((K_TOTAL / 32) * (N_TOTAL / 32)) // 1024

__global__ void __launch_bounds__(256)
cvt_kernel(const float* __restrict__ x, const float* __restrict__ m) {
    int tid = threadIdx.x;
    if (blockIdx.x < CVT_X_BLOCKS) {
        size_t i = ((size_t)blockIdx.x * 256 + tid) * 8;
        float4 a = *reinterpret_cast<const float4*>(x + i);
        float4 b = *reinterpret_cast<const float4*>(x + i + 4);
        uint4 o;
        o.x = pack_bf16x2(a.x, a.y);
        o.y = pack_bf16x2(a.z, a.w);
        o.z = pack_bf16x2(b.x, b.y);
        o.w = pack_bf16x2(b.z, b.w);
        *reinterpret_cast<uint4*>(g_xb + i) = o;
    } else {
        __shared__ float tile[32][33];
        int t = blockIdx.x - CVT_X_BLOCKS;
        int bn = (t & 31) * 32;          // n block
        int bk = (t >> 5) * 32;          // k block
        int lane = tid & 31;
        int rr = tid >> 5;               // 0..7
#pragma unroll
        for (int i = 0; i < 4; i++) {
            int row = i * 8 + rr;        // k within tile
            tile[row][lane] = m[(size_t)(bk + row) * N_TOTAL + bn + lane];
        }
        __syncthreads();
#pragma unroll
        for (int i = 0; i < 4; i++) {
            int row = i * 8 + rr;        // n within tile
            g_bt[(size_t)(bn + row) * K_TOTAL + bk + lane] =
                __float2bfloat16_rn(tile[lane][row]);
        }
    }
}

// ---------------------------------------------------------------------------
// GEMM + log kernel (persistent, cross-tile pipelined — R5 champion mainloop)
// ---------------------------------------------------------------------------
// Issue cp.asyncs for global chunk g (tile = first + (g>>4)*GRID, kc = g&15)
__device__ __forceinline__ void issue_chunk(uint32_t smem_base, int g, int first, int tid) {
    int t = first + (g >> 4) * GRID_GEMM;
    int kc = g & (NCHUNK - 1);
    int m0 = (t >> 3) * TILE_M;
    int n0 = (t & 7) * TILE_N;
    const uint4* Ag = reinterpret_cast<const uint4*>(g_xb + (size_t)m0 * K_TOTAL + kc * BK);
    const uint4* Bg = reinterpret_cast<const uint4*>(g_bt + (size_t)n0 * K_TOTAL + kc * BK);
    uint32_t Abase = smem_base + SMEM_TILES + (g % NSTAGE) * BUF_STRIDE;
    uint32_t Bbase = Abase + TILE_BYTES;
#pragma unroll
    for (int i = 0; i < 4; i++) {
        int cc = i * 256 + tid;           // 1024 16B-chunks per tile
        int row = cc >> 3;                // 0..127
        int c16 = cc & 7;                 // 16B chunk within 128B row
        uint32_t sw = sw128((uint32_t)(row * 128 + c16 * 16));
        cp_async16(Abase + sw, Ag + (size_t)row * (K_TOTAL / 8) + c16);
        cp_async16(Bbase + sw, Bg + (size_t)row * (K_TOTAL / 8) + c16);
    }
    CP_COMMIT();
}

__global__ void __launch_bounds__(256, 2)
logmm_gemm_kernel(float* __restrict__ out) {
    extern __shared__ char smem[];
    uint32_t sb = smem_u32(smem);
    int tid = threadIdx.x;
    int wid = tid >> 5;
    int lid = tid & 31;

    // 8 warps: warp_m in {0,1} (64 rows), warp_n in {0..3} (32 cols)
    int warp_m = wid >> 2;
    int warp_n = wid & 3;

    int first = blockIdx.x;
    int my_tiles = (NTILES - 1 - first) / GRID_GEMM + 1;  // 3 or 4
    int G = my_tiles * NCHUNK;

    float acc[4][4][4];
#pragma unroll
    for (int mf = 0; mf < 4; mf++)
#pragma unroll
        for (int nf = 0; nf < 4; nf++)
#pragma unroll
            for (int i = 0; i < 4; i++) acc[mf][nf][i] = 0.0f;

    // Prologue: fill 2 of 3 stages
    issue_chunk(sb, 0, first, tid);
    issue_chunk(sb, 1, first, tid);

    for (int g = 0; g < G; g++) {
        if (g == G - 1) { CP_WAIT(0); } else { CP_WAIT(1); }
        __syncthreads();

        // Prefetch chunk g+2 (may belong to the NEXT tile -> no drain)
        if (g + 2 < G) issue_chunk(sb, g + 2, first, tid);

        uint32_t Ab = sb + SMEM_TILES + (g % NSTAGE) * BUF_STRIDE;
        uint32_t Bb = Ab + TILE_BYTES;
#pragma unroll
        for (int ks = 0; ks < 4; ks++) {
            uint32_t a[4][4], b[2][4];
#pragma unroll
            for (int mf = 0; mf < 4; mf++) {
                int row = warp_m * 64 + mf * 16 + (lid & 15);
                uint32_t off = (uint32_t)(row * 128 + ks * 32 + ((lid >> 4) << 4));
                ldsm_x4(a[mf], Ab + sw128(off));
            }
#pragma unroll
            for (int p = 0; p < 2; p++) {
                int row = warp_n * 32 + p * 16 + (lid & 7) + ((lid >> 4) << 3);
                uint32_t off = (uint32_t)(row * 128 + ks * 32 + (((lid >> 3) & 1) << 4));
                ldsm_x4(b[p], Bb + sw128(off));
            }
#pragma unroll
            for (int mf = 0; mf < 4; mf++)
#pragma unroll
                for (int nf = 0; nf < 4; nf++)
                    mma16816(acc[mf][nf], a[mf], b[nf >> 1] + (nf & 1) * 2);
        }

        // Tile finished? Epilogue overlapped with in-flight next-tile loads.
        if ((g & (NCHUNK - 1)) == NCHUNK - 1) {
            int t = first + (g >> 4) * GRID_GEMM;
            int m0 = (t >> 3) * TILE_M;
            int n0 = (t & 7) * TILE_N;
#pragma unroll
            for (int mf = 0; mf < 4; mf++) {
#pragma unroll
                for (int nf = 0; nf < 4; nf++) {
                    int row0 = m0 + warp_m * 64 + mf * 16 + (lid >> 2);
                    int col = n0 + warp_n * 32 + nf * 8 + (lid & 3) * 2;
                    float2 v0, v1;
                    v0.x = __logf(fmaxf(acc[mf][nf][0], 1.17549435e-38f));
                    v0.y = __logf(fmaxf(acc[mf][nf][1], 1.17549435e-38f));
                    v1.x = __logf(fmaxf(acc[mf][nf][2], 1.17549435e-38f));
                    v1.y = __logf(fmaxf(acc[mf][nf][3], 1.17549435e-38f));
                    stg_cs_f2(out + (size_t)row0 * N_TOTAL + col, v0);
                    stg_cs_f2(out + (size_t)(row0 + 8) * N_TOTAL + col, v1);
                    acc[mf][nf][0] = 0.0f;
                    acc[mf][nf][1] = 0.0f;
                    acc[mf][nf][2] = 0.0f;
                    acc[mf][nf][3] = 0.0f;
                }
            }
        }
    }
}

// ---------------------------------------------------------------------------
// Launch
// ---------------------------------------------------------------------------
extern "C" void kernel_launch(void* const* d_in, const int* in_sizes, int n_in,
                              void* d_out, int out_size) {
    const float* x = (const float*)d_in[0];
    const float* mat = (const float*)d_in[1];
    if (n_in >= 2 && in_sizes[0] == N_TOTAL * K_TOTAL && in_sizes[1] == M_TOTAL * K_TOTAL) {
        const float* t = x; x = mat; mat = t;
    }
    float* out = (float*)d_out;

    cudaFuncSetAttribute(logmm_gemm_kernel,
                         cudaFuncAttributeMaxDynamicSharedMemorySize, SMEM_TOTAL);

    cvt_kernel<<<CVT_X_BLOCKS + CVT_T_BLOCKS, 256>>>(x, mat);
    logmm_gemm_kernel<<<GRID_GEMM, 256, SMEM_TOTAL>>>(out);
}

// round 15
// speedup vs baseline: 1.3460x; 1.0006x over previous
#include <cuda_runtime.h>
#include <cuda_bf16.h>
#include <cstdint>

// ============================================================================
// LogMM: out[16384,1024] = log( x[16384,1024] @ matrix[1024,1024] )
// (reference's big/small branches sum exactly to log(max(y,tiny)))
//
// R15: champion (R14, 100.9us) + two measured-fact deltas:
//  1) GRID_GEMM 296 -> 304: GB300 has 152 SMs (not 148); 2 CTAs on every SM,
//     4 more tensor pipes online, mean tiles/SM 6.92 -> 6.74.
//  2) cvt kernel reads its read-once fp32 sources with ld.global.cs so they
//     don't evict the bf16 outputs the GEMM immediately re-reads from L2.
// Mainloop otherwise byte-identical to the banked optimum.
// ============================================================================

#define M_TOTAL 16384
#define N_TOTAL 1024
#define K_TOTAL 1024
#define TILE_M 128
#define TILE_N 128
#define BK 64                    // bf16 per K-chunk (128 B per row)
#define NCHUNK (K_TOTAL / BK)    // 16
#define NSTAGE 3
#define NTILES ((M_TOTAL / TILE_M) * (N_TOTAL / TILE_N))  // 1024
#define GRID_GEMM 304            // 2 CTAs/SM x 152 SMs (GB300)

static constexpr int SMEM_TILES = 1024;
static constexpr int TILE_BYTES = TILE_M * 128;     // 16384
static constexpr int BUF_STRIDE = 2 * TILE_BYTES;   // 32768
static constexpr int SMEM_TOTAL = SMEM_TILES + NSTAGE * BUF_STRIDE;  // 99328

// Scratch bf16 buffers (device globals: allocation-free)
__device__ __align__(256) __nv_bfloat16 g_xb[(size_t)M_TOTAL * K_TOTAL];
__device__ __align__(256) __nv_bfloat16 g_bt[(size_t)N_TOTAL * K_TOTAL];

// ---------------------------------------------------------------------------
// Helpers
// ---------------------------------------------------------------------------
__device__ __forceinline__ uint32_t smem_u32(const void* p) {
    uint32_t a;
    asm("{ .reg .u64 t; cvta.to.shared.u64 t, %1; cvt.u32.u64 %0, t; }" : "=r"(a) : "l"(p));
    return a;
}
__device__ __forceinline__ uint32_t sw128(uint32_t off) {
    return off ^ ((off >> 3) & 0x70);
}
__device__ __forceinline__ void cp_async16(uint32_t smem_addr, const void* gptr) {
    asm volatile("cp.async.cg.shared.global [%0], [%1], 16;"
                 :: "r"(smem_addr), "l"(gptr) : "memory");
}
#define CP_COMMIT() asm volatile("cp.async.commit_group;" ::: "memory")
#define CP_WAIT(n)  asm volatile("cp.async.wait_group %0;" :: "n"(n) : "memory")

__device__ __forceinline__ void ldsm_x4(uint32_t* r, uint32_t addr) {
    asm volatile("ldmatrix.sync.aligned.m8n8.x4.shared.b16 {%0, %1, %2, %3}, [%4];"
                 : "=r"(r[0]), "=r"(r[1]), "=r"(r[2]), "=r"(r[3]) : "r"(addr));
}
__device__ __forceinline__ void mma16816(float* c, const uint32_t* a, const uint32_t* b) {
    asm volatile("mma.sync.aligned.m16n8k16.row.col.f32.bf16.bf16.f32 "
                 "{%0, %1, %2, %3}, {%4, %5, %6, %7}, {%8, %9}, {%0, %1, %2, %3};"
                 : "+f"(c[0]), "+f"(c[1]), "+f"(c[2]), "+f"(c[3])
                 : "r"(a[0]), "r"(a[1]), "r"(a[2]), "r"(a[3]), "r"(b[0]), "r"(b[1]));
}
__device__ __forceinline__ uint32_t pack_bf16x2(float a, float b) {
    __nv_bfloat162 h = __floats2bfloat162_rn(a, b);
    return *reinterpret_cast<uint32_t*>(&h);
}
// Streaming (evict-first) output store: write-once, don't pollute L2.
__device__ __forceinline__ void stg_cs_f2(float* p, float2 v) {
    asm volatile("st.global.cs.v2.f32 [%0], {%1, %2};"
                 :: "l"(p), "f"(v.x), "f"(v.y) : "memory");
}
// Streaming (evict-first) read-once fp32 source loads.
__device__ __forceinline__ float4 ldg_cs_f4(const float* p) {
    float4 v;
    asm volatile("ld.global.cs.v4.f32 {%0, %1, %2, %3}, [%4];"
                 : "=f"(v.x), "=f"(v.y), "=f"(v.z), "=f"(v.w) : "l"(p));
    return v;
}
__device__ __forceinline__ float ldg_cs_f(const float* p) {
    float v;
    asm volatile("ld.global.cs.f32 %0, [%1];" : "=f"(v) : "l"(p));
    return v;
}

// ---------------------------------------------------------------------------
// Fused conversion kernel (single launch):
//   blocks [0, 8192):         x fp32 -> g_xb bf16 (8 elems/thread)
//   blocks [8192, 8192+1024): matrix[K,N] -> g_bt[N,K] bf16 (32x32 tiles)
// ---------------------------------------------------------------------------
#define CVT_X_BLOCKS (M_TOTAL * K_TOTAL / (256 * 8))   // 8192
#define CVT_T_BLOCKS ((K_TOTAL / 32) * (N_TOTAL / 32)) // 1024

__global__ void __launch_bounds__(256)
cvt_kernel(const float* __restrict__ x, const float* __restrict__ m) {
    int tid = threadIdx.x;
    if (blockIdx.x < CVT_X_BLOCKS) {
        size_t i = ((size_t)blockIdx.x * 256 + tid) * 8;
        float4 a = ldg_cs_f4(x + i);
        float4 b = ldg_cs_f4(x + i + 4);
        uint4 o;
        o.x = pack_bf16x2(a.x, a.y);
        o.y = pack_bf16x2(a.z, a.w);
        o.z = pack_bf16x2(b.x, b.y);
        o.w = pack_bf16x2(b.z, b.w);
        *reinterpret_cast<uint4*>(g_xb + i) = o;
    } else {
        __shared__ float tile[32][33];
        int t = blockIdx.x - CVT_X_BLOCKS;
        int bn = (t & 31) * 32;          // n block
        int bk = (t >> 5) * 32;          // k block
        int lane = tid & 31;
        int rr = tid >> 5;               // 0..7
#pragma unroll
        for (int i = 0; i < 4; i++) {
            int row = i * 8 + rr;        // k within tile
            tile[row][lane] = ldg_cs_f(m + (size_t)(bk + row) * N_TOTAL + bn + lane);
        }
        __syncthreads();
#pragma unroll
        for (int i = 0; i < 4; i++) {
            int row = i * 8 + rr;        // n within tile
            g_bt[(size_t)(bn + row) * K_TOTAL + bk + lane] =
                __float2bfloat16_rn(tile[lane][row]);
        }
    }
}

// ---------------------------------------------------------------------------
// GEMM + log kernel (persistent, cross-tile pipelined — champion mainloop)
// ---------------------------------------------------------------------------
// Issue cp.asyncs for global chunk g (tile = first + (g>>4)*GRID, kc = g&15)
__device__ __forceinline__ void issue_chunk(uint32_t smem_base, int g, int first, int tid) {
    int t = first + (g >> 4) * GRID_GEMM;
    int kc = g & (NCHUNK - 1);
    int m0 = (t >> 3) * TILE_M;
    int n0 = (t & 7) * TILE_N;
    const uint4* Ag = reinterpret_cast<const uint4*>(g_xb + (size_t)m0 * K_TOTAL + kc * BK);
    const uint4* Bg = reinterpret_cast<const uint4*>(g_bt + (size_t)n0 * K_TOTAL + kc * BK);
    uint32_t Abase = smem_base + SMEM_TILES + (g % NSTAGE) * BUF_STRIDE;
    uint32_t Bbase = Abase + TILE_BYTES;
#pragma unroll
    for (int i = 0; i < 4; i++) {
        int cc = i * 256 + tid;           // 1024 16B-chunks per tile
        int row = cc >> 3;                // 0..127
        int c16 = cc & 7;                 // 16B chunk within 128B row
        uint32_t sw = sw128((uint32_t)(row * 128 + c16 * 16));
        cp_async16(Abase + sw, Ag + (size_t)row * (K_TOTAL / 8) + c16);
        cp_async16(Bbase + sw, Bg + (size_t)row * (K_TOTAL / 8) + c16);
    }
    CP_COMMIT();
}

__global__ void __launch_bounds__(256, 2)
logmm_gemm_kernel(float* __restrict__ out) {
    extern __shared__ char smem[];
    uint32_t sb = smem_u32(smem);
    int tid = threadIdx.x;
    int wid = tid >> 5;
    int lid = tid & 31;

    // 8 warps: warp_m in {0,1} (64 rows), warp_n in {0..3} (32 cols)
    int warp_m = wid >> 2;
    int warp_n = wid & 3;

    int first = blockIdx.x;
    int my_tiles = (NTILES - 1 - first) / GRID_GEMM + 1;  // 4 (first 112) or 3
    int G = my_tiles * NCHUNK;

    float acc[4][4][4];
#pragma unroll
    for (int mf = 0; mf < 4; mf++)
#pragma unroll
        for (int nf = 0; nf < 4; nf++)
#pragma unroll
            for (int i = 0; i < 4; i++) acc[mf][nf][i] = 0.0f;

    // Prologue: fill 2 of 3 stages
    issue_chunk(sb, 0, first, tid);
    issue_chunk(sb, 1, first, tid);

    for (int g = 0; g < G; g++) {
        if (g == G - 1) { CP_WAIT(0); } else { CP_WAIT(1); }
        __syncthreads();

        // Prefetch chunk g+2 (may belong to the NEXT tile -> no drain)
        if (g + 2 < G) issue_chunk(sb, g + 2, first, tid);

        uint32_t Ab = sb + SMEM_TILES + (g % NSTAGE) * BUF_STRIDE;
        uint32_t Bb = Ab + TILE_BYTES;
#pragma unroll
        for (int ks = 0; ks < 4; ks++) {
            uint32_t a[4][4], b[2][4];
#pragma unroll
            for (int mf = 0; mf < 4; mf++) {
                int row = warp_m * 64 + mf * 16 + (lid & 15);
                uint32_t off = (uint32_t)(row * 128 + ks * 32 + ((lid >> 4) << 4));
                ldsm_x4(a[mf], Ab + sw128(off));
            }
#pragma unroll
            for (int p = 0; p < 2; p++) {
                int row = warp_n * 32 + p * 16 + (lid & 7) + ((lid >> 4) << 3);
                uint32_t off = (uint32_t)(row * 128 + ks * 32 + (((lid >> 3) & 1) << 4));
                ldsm_x4(b[p], Bb + sw128(off));
            }
#pragma unroll
            for (int mf = 0; mf < 4; mf++)
#pragma unroll
                for (int nf = 0; nf < 4; nf++)
                    mma16816(acc[mf][nf], a[mf], b[nf >> 1] + (nf & 1) * 2);
        }

        // Tile finished? Epilogue overlapped with in-flight next-tile loads.
        if ((g & (NCHUNK - 1)) == NCHUNK - 1) {
            int t = first + (g >> 4) * GRID_GEMM;
            int m0 = (t >> 3) * TILE_M;
            int n0 = (t & 7) * TILE_N;
#pragma unroll
            for (int mf = 0; mf < 4; mf++) {
#pragma unroll
                for (int nf = 0; nf < 4; nf++) {
                    int row0 = m0 + warp_m * 64 + mf * 16 + (lid >> 2);
                    int col = n0 + warp_n * 32 + nf * 8 + (lid & 3) * 2;
                    float2 v0, v1;
                    v0.x = __logf(fmaxf(acc[mf][nf][0], 1.17549435e-38f));
                    v0.y = __logf(fmaxf(acc[mf][nf][1], 1.17549435e-38f));
                    v1.x = __logf(fmaxf(acc[mf][nf][2], 1.17549435e-38f));
                    v1.y = __logf(fmaxf(acc[mf][nf][3], 1.17549435e-38f));
                    stg_cs_f2(out + (size_t)row0 * N_TOTAL + col, v0);
                    stg_cs_f2(out + (size_t)(row0 + 8) * N_TOTAL + col, v1);
                    acc[mf][nf][0] = 0.0f;
                    acc[mf][nf][1] = 0.0f;
                    acc[mf][nf][2] = 0.0f;
                    acc[mf][nf][3] = 0.0f;
                }
            }
        }
    }
}

// ---------------------------------------------------------------------------
// Launch
// ---------------------------------------------------------------------------
extern "C" void kernel_launch(void* const* d_in, const int* in_sizes, int n_in,
                              void* d_out, int out_size) {
    const float* x = (const float*)d_in[0];
    const float* mat = (const float*)d_in[1];
    if (n_in >= 2 && in_sizes[0] == N_TOTAL * K_TOTAL && in_sizes[1] == M_TOTAL * K_TOTAL) {
        const float* t = x; x = mat; mat = t;
    }
    float* out = (float*)d_out;

    cudaFuncSetAttribute(logmm_gemm_kernel,
                         cudaFuncAttributeMaxDynamicSharedMemorySize, SMEM_TOTAL);

    cvt_kernel<<<CVT_X_BLOCKS + CVT_T_BLOCKS, 256>>>(x, mat);
    logmm_gemm_kernel<<<GRID_GEMM, 256, SMEM_TOTAL>>>(out);
}